// round 1
// baseline (speedup 1.0000x reference)
#include <cuda_runtime.h>
#include <cstdint>
#include <cstdio>

// Problem sizes (fixed by reference_code)
#define NN0 500000
#define NN1 100000
#define NN2 25000
#define EE0 1600000
#define EE1 400000
#define DIN 128
#define DH  256
#define DOUT 128

// ---------------- device scratch (no allocations allowed) ----------------
// float4 typing forces 16B alignment.
__device__ float4 g_agg0[(size_t)NN1 * DIN / 4];   // 51.2 MB
__device__ float4 g_cnt0[NN1 / 4];                 // 0.4 MB
__device__ float4 g_h   [(size_t)NN1 * DH / 4];    // 102.4 MB
__device__ float4 g_agg1[(size_t)NN2 * DH / 4];    // 25.6 MB
__device__ float4 g_cnt1[NN2 / 4];                 // 0.1 MB

// ---------------- zero scratch ----------------
#define Z_AGG0 ((size_t)NN1 * DIN / 4)   // 3,200,000
#define Z_AGG1 ((size_t)NN2 * DH  / 4)   // 1,600,000
#define Z_CNT0 ((size_t)NN1 / 4)         // 25,000
#define Z_CNT1 ((size_t)NN2 / 4)         // 6,250
#define Z_TOTAL (Z_AGG0 + Z_AGG1 + Z_CNT0 + Z_CNT1)  // 4,831,250

__global__ void zero_scratch_kernel() {
    size_t i = (size_t)blockIdx.x * blockDim.x + threadIdx.x;
    if (i >= Z_TOTAL) return;
    const float4 z = make_float4(0.f, 0.f, 0.f, 0.f);
    if (i < Z_AGG0) { g_agg0[i] = z; return; }
    i -= Z_AGG0;
    if (i < Z_AGG1) { g_agg1[i] = z; return; }
    i -= Z_AGG1;
    if (i < Z_CNT0) { g_cnt0[i] = z; return; }
    i -= Z_CNT0;
    g_cnt1[i] = z;
}

// ---------------- edge scatter (atomic mean accumulation) ----------------
__device__ __forceinline__ void red_add_f4(float4* p, float4 v) {
    asm volatile("red.global.add.v4.f32 [%0], {%1,%2,%3,%4};"
                 :: "l"(p), "f"(v.x), "f"(v.y), "f"(v.z), "f"(v.w)
                 : "memory");
}

// one warp per edge, 128 floats = 32 float4 lanes
__global__ void scatter0_kernel(const float4* __restrict__ x4,
                                const int* __restrict__ es,
                                const int* __restrict__ ed) {
    unsigned gtid = blockIdx.x * 256u + threadIdx.x;
    unsigned e = gtid >> 5;           // grid sized exactly: E0*32/256 blocks
    int lane = gtid & 31;
    int src = es[e];
    int dst = ed[e];
    float4 v = __ldg(&x4[(size_t)src * 32 + lane]);
    red_add_f4(&g_agg0[(size_t)dst * 32 + lane], v);
    if (lane == 0) atomicAdd((float*)g_cnt0 + dst, 1.0f);
}

// 64 threads per edge, 256 floats = 64 float4 lanes, reads g_h
__global__ void scatter1_kernel(const int* __restrict__ es,
                                const int* __restrict__ ed) {
    unsigned gtid = blockIdx.x * 256u + threadIdx.x;
    unsigned e = gtid >> 6;           // grid sized exactly: E1*64/256 blocks
    int lane = gtid & 63;
    int src = es[e];
    int dst = ed[e];
    float4 v = g_h[(size_t)src * 64 + lane];
    red_add_f4(&g_agg1[(size_t)dst * 64 + lane], v);
    if (lane == 0) atomicAdd((float*)g_cnt1 + dst, 1.0f);
}

// ---------------- fused SAGEConv GEMM ----------------
// out[m,n] = act( sum_k (A0[m,k]/max(cnt[m],1)) * B0[n,k]
//               + sum_k  A1[m,k]              * B1[n,k] + bias[n] )
// A0,A1: [M, D] row-major.  B0,B1: [N, D] row-major.  out: [M, N].
// Tile: 128 x 64, TK=16, 256 threads, 8x4 register tile per thread.
template<int D>
__global__ __launch_bounds__(256)
void sage_gemm_kernel(const float* __restrict__ A0, const float* __restrict__ cnt,
                      const float* __restrict__ A1,
                      const float* __restrict__ B0, const float* __restrict__ B1,
                      const float* __restrict__ bias,
                      float* __restrict__ out,
                      int M, int N, int do_relu) {
    constexpr int TM = 128, TN = 64, TK = 16;
    __shared__ float As[TK][TM + 4];
    __shared__ float Bs[TK][TN + 4];

    const int tid = threadIdx.x;
    const int tx = tid & 15;          // 16 col-groups of 4
    const int ty = tid >> 4;          // 16 row-groups of 8
    const int row0 = blockIdx.x * TM;
    const int col0 = blockIdx.y * TN;

    float acc[8][4];
#pragma unroll
    for (int i = 0; i < 8; ++i)
#pragma unroll
        for (int j = 0; j < 4; ++j) acc[i][j] = 0.f;

#pragma unroll 1
    for (int half = 0; half < 2; ++half) {
        const float* __restrict__ A = half ? A1 : A0;
        const float* __restrict__ B = half ? B1 : B0;
#pragma unroll 1
        for (int kb = 0; kb < D; kb += TK) {
            // --- load A tile: 128x16 floats = 512 float4, 2 per thread ---
#pragma unroll
            for (int it = 0; it < 2; ++it) {
                int i = tid + it * 256;
                int m  = i >> 2;
                int k4 = (i & 3) * 4;
                int row = row0 + m;
                float4 v = make_float4(0.f, 0.f, 0.f, 0.f);
                float s = 1.0f;
                if (row < M) {
                    v = *(const float4*)(A + (size_t)row * D + kb + k4);
                    if (half == 0) s = 1.0f / fmaxf(__ldg(cnt + row), 1.0f);
                }
                As[k4 + 0][m] = v.x * s;
                As[k4 + 1][m] = v.y * s;
                As[k4 + 2][m] = v.z * s;
                As[k4 + 3][m] = v.w * s;
            }
            // --- load B tile: 64x16 floats = 256 float4, 1 per thread ---
            {
                int n  = tid >> 2;
                int k4 = (tid & 3) * 4;
                float4 v = *(const float4*)(B + (size_t)(col0 + n) * D + kb + k4);
                Bs[k4 + 0][n] = v.x;
                Bs[k4 + 1][n] = v.y;
                Bs[k4 + 2][n] = v.z;
                Bs[k4 + 3][n] = v.w;
            }
            __syncthreads();
            // --- compute ---
#pragma unroll
            for (int k = 0; k < TK; ++k) {
                float a[8], b[4];
#pragma unroll
                for (int i = 0; i < 8; ++i) a[i] = As[k][ty * 8 + i];
#pragma unroll
                for (int j = 0; j < 4; ++j) b[j] = Bs[k][tx * 4 + j];
#pragma unroll
                for (int i = 0; i < 8; ++i)
#pragma unroll
                    for (int j = 0; j < 4; ++j) acc[i][j] += a[i] * b[j];
            }
            __syncthreads();
        }
    }

    // --- epilogue: bias + optional relu ---
#pragma unroll
    for (int i = 0; i < 8; ++i) {
        int row = row0 + ty * 8 + i;
        if (row >= M) continue;
#pragma unroll
        for (int j = 0; j < 4; ++j) {
            int col = col0 + tx * 4 + j;
            float v = acc[i][j] + __ldg(bias + col);
            if (do_relu) v = fmaxf(v, 0.f);
            out[(size_t)row * N + col] = v;
        }
    }
}

// ---------------- host launcher ----------------
extern "C" void kernel_launch(void* const* d_in, const int* in_sizes, int n_in,
                              void* d_out, int out_size) {
    const float* x   = (const float*)d_in[0];
    const float* Wl0 = (const float*)d_in[1];
    const float* bl0 = (const float*)d_in[2];
    const float* Wr0 = (const float*)d_in[3];
    const float* Wl1 = (const float*)d_in[4];
    const float* bl1 = (const float*)d_in[5];
    const float* Wr1 = (const float*)d_in[6];
    const int* e0s = (const int*)d_in[7];
    const int* e0d = (const int*)d_in[8];
    const int* e1s = (const int*)d_in[9];
    const int* e1d = (const int*)d_in[10];
    float* out = (float*)d_out;

    void *p_agg0, *p_cnt0, *p_h, *p_agg1, *p_cnt1;
    cudaGetSymbolAddress(&p_agg0, g_agg0);
    cudaGetSymbolAddress(&p_cnt0, g_cnt0);
    cudaGetSymbolAddress(&p_h,    g_h);
    cudaGetSymbolAddress(&p_agg1, g_agg1);
    cudaGetSymbolAddress(&p_cnt1, g_cnt1);

    // 1. zero accumulators
    {
        int blocks = (int)((Z_TOTAL + 255) / 256);
        zero_scratch_kernel<<<blocks, 256>>>();
    }
    // 2. hop-0 scatter: E0 edges * 32 lanes = 51.2M threads -> 200000 blocks
    scatter0_kernel<<<EE0 * 32 / 256, 256>>>((const float4*)x, e0s, e0d);

    // 3. hop-0 dense: h = relu([agg0/cnt | x[:N1]] @ [Wl0|Wr0]^T + b)
    {
        dim3 grid((NN1 + 127) / 128, DH / 64);
        sage_gemm_kernel<DIN><<<grid, 256>>>(
            (const float*)p_agg0, (const float*)p_cnt0, x,
            Wl0, Wr0, bl0, (float*)p_h, NN1, DH, /*relu=*/1);
    }
    // 4. hop-1 scatter: E1 edges * 64 lanes = 25.6M threads -> 100000 blocks
    scatter1_kernel<<<EE1 * 64 / 256, 256>>>(e1s, e1d);

    // 5. hop-1 dense: out = [agg1/cnt | h[:N2]] @ [Wl1|Wr1]^T + b
    {
        dim3 grid((NN2 + 127) / 128, DOUT / 64);
        sage_gemm_kernel<DH><<<grid, 256>>>(
            (const float*)p_agg1, (const float*)p_cnt1, (const float*)p_h,
            Wl1, Wr1, bl1, out, NN2, DOUT, /*relu=*/0);
    }
    (void)in_sizes; (void)n_in; (void)out_size;
}